// round 1
// baseline (speedup 1.0000x reference)
#include <cuda_runtime.h>
#include <cuda_fp16.h>

#define H      32
#define NN     64
#define MHD_   5
#define NEDGE  1025   // NUM_EDGE_EMB
#define ROWLEN 65     // N + 1

// Precombined table: M[d][i][k] = sum_h W_edge[i][h] * W_dist[(d*32+h)*32 + k]
// 5 * 1025 * 32 halves = 328 KB (static device scratch; no allocations).
__device__ __half d_M[MHD_ * NEDGE * H];

// ---------------------------------------------------------------------------
// Prologue: fold W_edge (1025x32) with Wd (5x32x32) into fp16 M.
// 1025 blocks x 160 threads (one warp per d). ~5.2M FMAs, trivial.
// ---------------------------------------------------------------------------
__global__ __launch_bounds__(160) void precompute_M(
    const float* __restrict__ W_edge,
    const float* __restrict__ W_dist)
{
    int i    = blockIdx.x;            // edge-embedding row 0..1024
    int d    = threadIdx.x >> 5;      // 0..4
    int lane = threadIdx.x & 31;      // output head k

    float we = W_edge[i * H + lane];  // lane holds W_edge[i][lane]
    float acc = 0.f;
    #pragma unroll
    for (int h = 0; h < H; ++h) {
        float w = __shfl_sync(0xffffffffu, we, h);
        acc = fmaf(w, __ldg(&W_dist[(d * H + h) * H + lane]), acc);
    }
    d_M[(d * NEDGE + i) * H + lane] = __float2half(acc);
}

// ---------------------------------------------------------------------------
// Main kernel: grid = B * (N+1). blockIdx -> (b, out-row r).
//   r == 0  : out[b,h,0,j]   = attn_bias + w_token[h]          (all j)
//   r >= 1  : out[b,h,r,0]   = attn_bias + w_token[h]
//             out[b,h,r,1+m] = attn_bias + W_spatial[sp,h]
//                              + (1/sp_) * sum_d (sum_f M[d,idx,h]) / cnt_d
// Bias tile (64 m x 32 h) staged in smem (pad 33 -> conflict-free transpose),
// then written coalesced per head row (65 contiguous floats).
// ---------------------------------------------------------------------------
__global__ __launch_bounds__(256) void graph_attn_bias_kernel(
    const float* __restrict__ attn_bias,
    const int*   __restrict__ spatial_pos,
    const int*   __restrict__ edge_input,
    const float* __restrict__ W_spatial,
    const float* __restrict__ w_token,
    float*       __restrict__ out)
{
    const int bidx = blockIdx.x;
    const int b    = bidx / ROWLEN;
    const int r    = bidx - b * ROWLEN;
    const int tid  = threadIdx.x;

    if (r == 0) {
        // Top border row: 32 heads x 65 cols, attn_bias + w_token[h].
        const float* ab = attn_bias + (size_t)b * H * ROWLEN * ROWLEN;
        float*       o  = out       + (size_t)b * H * ROWLEN * ROWLEN;
        for (int t = tid; t < H * ROWLEN; t += 256) {
            int h = t / ROWLEN;
            int j = t - h * ROWLEN;
            size_t idx = (size_t)h * (ROWLEN * ROWLEN) + j;
            o[idx] = ab[idx] + __ldg(&w_token[h]);
        }
        return;
    }
    const int n = r - 1;   // graph row 0..63

    __shared__ int   s_eidx[NN * 15];  // 3.75 KB  edge indices for this row
    __shared__ int   s_sp[NN];         // spatial_pos for this row
    __shared__ float s_tile[NN * 33];  // bias[m][h], padded

    // Stage this row's edge indices (64 pairs * 15 ints, contiguous) + spatial.
    const int* ebase = edge_input + (size_t)(b * NN + n) * NN * 15;
    for (int t = tid; t < NN * 15; t += 256) s_eidx[t] = ebase[t];
    const int* sbase = spatial_pos + (size_t)(b * NN + n) * NN;
    if (tid < NN) s_sp[tid] = sbase[tid];
    __syncthreads();

    const int warp = tid >> 5;
    const int lane = tid & 31;   // = head index

    #pragma unroll
    for (int mi = 0; mi < 8; ++mi) {
        const int m  = warp * 8 + mi;
        const int sp = s_sp[m];
        const float spb = __ldg(&W_spatial[sp * H + lane]);

        float acc = 0.f;
        #pragma unroll
        for (int d = 0; d < MHD_; ++d) {
            const int i0 = s_eidx[m * 15 + d * 3 + 0];
            const int i1 = s_eidx[m * 15 + d * 3 + 1];
            const int i2 = s_eidx[m * 15 + d * 3 + 2];
            float a = 0.f;
            int   c = 0;
            // Predicates are warp-uniform (same idx for all lanes): no divergence.
            if (i0) { a += __half2float(d_M[(d * NEDGE + i0) * H + lane]); ++c; }
            if (i1) { a += __half2float(d_M[(d * NEDGE + i1) * H + lane]); ++c; }
            if (i2) { a += __half2float(d_M[(d * NEDGE + i2) * H + lane]); ++c; }
            if (c)  { acc += a / (float)c; }
        }
        int spc = sp - 1;
        spc = spc < 1 ? 1 : (spc > MHD_ ? MHD_ : spc);
        s_tile[m * 33 + lane] = spb + acc / (float)spc;
    }
    __syncthreads();

    // Write row (n+1): 32 heads x 65 cols; j==0 gets w_token, j>=1 gets tile.
    const float* ab = attn_bias + ((size_t)b * H * ROWLEN + (n + 1)) * ROWLEN;
    float*       o  = out       + ((size_t)b * H * ROWLEN + (n + 1)) * ROWLEN;
    for (int t = tid; t < H * ROWLEN; t += 256) {
        int h = t / ROWLEN;
        int j = t - h * ROWLEN;
        size_t idx = (size_t)h * (ROWLEN * ROWLEN) + j;
        float v = (j == 0) ? __ldg(&w_token[h]) : s_tile[(j - 1) * 33 + h];
        o[idx] = ab[idx] + v;
    }
}

// ---------------------------------------------------------------------------
// Inputs (metadata order):
//  0 attn_bias  f32 (64,32,65,65)
//  1 spatial_pos i32 (64,64,64)
//  2 edge_input  i32 (64,64,64,5,3)
//  3 attn_edge_type i32 (unused by reference)
//  4 W_edge     f32 (1025,32)
//  5 W_dist     f32 (131072,1)
//  6 W_spatial  f32 (512,32)
//  7 w_token    f32 (1,32)
// ---------------------------------------------------------------------------
extern "C" void kernel_launch(void* const* d_in, const int* in_sizes, int n_in,
                              void* d_out, int out_size)
{
    const float* attn_bias   = (const float*)d_in[0];
    const int*   spatial_pos = (const int*)  d_in[1];
    const int*   edge_input  = (const int*)  d_in[2];
    const float* W_edge      = (const float*)d_in[4];
    const float* W_dist      = (const float*)d_in[5];
    const float* W_spatial   = (const float*)d_in[6];
    const float* w_token     = (const float*)d_in[7];
    float*       out         = (float*)d_out;

    precompute_M<<<NEDGE, 160>>>(W_edge, W_dist);
    graph_attn_bias_kernel<<<64 * ROWLEN, 256>>>(
        attn_bias, spatial_pos, edge_input, W_spatial, w_token, out);
}

// round 2
// speedup vs baseline: 2.5241x; 2.5241x over previous
#include <cuda_runtime.h>
#include <cuda_fp16.h>

#define H      32
#define NN     64
#define MHD_   5
#define NEDGE  1025   // NUM_EDGE_EMB
#define ROWLEN 65     // N + 1

// Precombined table M[d][i][k] = sum_h W_edge[i][h] * Wd[d][h][k],
// stored as half2 pairs over k: M2[(d*NEDGE+i)*16 + hh] = {k=2hh, k=2hh+1}.
// 5*1025*16 half2 = 328 KB static scratch (8B-aligned for half2 loads).
__device__ __half2 d_M2[MHD_ * NEDGE * (H / 2)];

// ---------------------------------------------------------------------------
// Prologue: fold W_edge (1025x32) with Wd (5x32x32) into fp16 M.
// ---------------------------------------------------------------------------
__global__ __launch_bounds__(160) void precompute_M(
    const float* __restrict__ W_edge,
    const float* __restrict__ W_dist)
{
    int i    = blockIdx.x;            // edge-embedding row 0..1024
    int d    = threadIdx.x >> 5;      // 0..4
    int lane = threadIdx.x & 31;      // output head k

    float we = W_edge[i * H + lane];
    float acc = 0.f;
    #pragma unroll
    for (int h = 0; h < H; ++h) {
        float w = __shfl_sync(0xffffffffu, we, h);
        acc = fmaf(w, __ldg(&W_dist[(d * H + h) * H + lane]), acc);
    }
    ((__half*)d_M2)[(d * NEDGE + i) * H + lane] = __float2half(acc);
}

// ---------------------------------------------------------------------------
// Main kernel: grid = B * (N+1), 256 threads.
// Half2 over heads: 16 lanes per m, warp handles 2 m per pass (4 passes).
// ---------------------------------------------------------------------------
__global__ __launch_bounds__(256, 6) void graph_attn_bias_kernel(
    const float* __restrict__ attn_bias,
    const int*   __restrict__ spatial_pos,
    const int*   __restrict__ edge_input,
    const float* __restrict__ W_spatial,
    const float* __restrict__ w_token,
    float*       __restrict__ out)
{
    const int bidx = blockIdx.x;
    const int b    = bidx / ROWLEN;
    const int r    = bidx - b * ROWLEN;
    const int tid  = threadIdx.x;
    const int warp = tid >> 5;
    const int lane = tid & 31;

    if (r == 0) {
        // Top border row: out[b,h,0,j] = attn_bias + w_token[h].
        const float* ab = attn_bias + (size_t)b * H * (ROWLEN * ROWLEN);
        float*       o  = out       + (size_t)b * H * (ROWLEN * ROWLEN);
        #pragma unroll
        for (int k = 0; k < 4; ++k) {
            int h = warp * 4 + k;
            float gt = __ldg(&w_token[h]);
            size_t base = (size_t)h * (ROWLEN * ROWLEN);
            o[base + lane]      = ab[base + lane]      + gt;
            o[base + 32 + lane] = ab[base + 32 + lane] + gt;
            if (lane == 0) o[base + 64] = ab[base + 64] + gt;
        }
        return;
    }
    const int n = r - 1;   // graph row 0..63

    __shared__ int   s_eidx[NN * 15];  // edge indices for this row
    __shared__ int   s_sp[NN];         // spatial_pos for this row
    __shared__ float s_tile[NN * 33];  // bias[m][h], padded (33 odd -> no conflicts)

    const int* ebase = edge_input + (size_t)(b * NN + n) * NN * 15;
    for (int t = tid; t < NN * 15; t += 256) s_eidx[t] = ebase[t];
    if (tid < NN) s_sp[tid] = spatial_pos[(size_t)(b * NN + n) * NN + tid];
    __syncthreads();

    const int p  = lane >> 4;   // which of the 2 m this half-warp owns
    const int hh = lane & 15;   // half2 head-pair index (heads 2hh, 2hh+1)
    const __half2 z2 = __float2half2_rn(0.f);

    #pragma unroll
    for (int mi = 0; mi < 4; ++mi) {
        const int m  = warp * 8 + mi * 2 + p;
        const int sp = s_sp[m];
        const float2 spb = __ldg((const float2*)W_spatial + sp * (H / 2) + hh);

        float2 acc = make_float2(0.f, 0.f);
        #pragma unroll
        for (int d = 0; d < MHD_; ++d) {
            const int i0 = s_eidx[m * 15 + d * 3 + 0];
            const int i1 = s_eidx[m * 15 + d * 3 + 1];
            const int i2 = s_eidx[m * 15 + d * 3 + 2];
            __half2 v0 = i0 ? d_M2[(d * NEDGE + i0) * (H / 2) + hh] : z2;
            __half2 v1 = i1 ? d_M2[(d * NEDGE + i1) * (H / 2) + hh] : z2;
            __half2 v2 = i2 ? d_M2[(d * NEDGE + i2) * (H / 2) + hh] : z2;
            int c = (i0 != 0) + (i1 != 0) + (i2 != 0);
            // reciprocal-of-count: c==0 -> 0, c==1 -> 1, c==2 -> 1/2, c==3 -> 1/3
            float rc = (c == 3) ? (1.f / 3.f) : (c == 2 ? 0.5f : (float)c);
            float2 a = __half22float2(__hadd2(__hadd2(v0, v1), v2));
            acc.x = fmaf(a.x, rc, acc.x);
            acc.y = fmaf(a.y, rc, acc.y);
        }
        int spc = sp - 1;
        spc = spc < 1 ? 1 : (spc > MHD_ ? MHD_ : spc);
        float rs = (spc == 1) ? 1.f
                 : (spc == 2) ? 0.5f
                 : (spc == 3) ? (1.f / 3.f)
                 : (spc == 4) ? 0.25f : 0.2f;
        s_tile[m * 33 + 2 * hh]     = fmaf(acc.x, rs, spb.x);
        s_tile[m * 33 + 2 * hh + 1] = fmaf(acc.y, rs, spb.y);
    }
    __syncthreads();

    // Write row (n+1): warp -> 4 heads, lane -> column; j==0 takes w_token.
    const float* ab = attn_bias + ((size_t)b * H * ROWLEN + (n + 1)) * ROWLEN;
    float*       o  = out       + ((size_t)b * H * ROWLEN + (n + 1)) * ROWLEN;
    #pragma unroll
    for (int k = 0; k < 4; ++k) {
        int h = warp * 4 + k;
        size_t base = (size_t)h * (ROWLEN * ROWLEN);
        float v0 = (lane == 0) ? __ldg(&w_token[h]) : s_tile[(lane - 1) * 33 + h];
        o[base + lane] = ab[base + lane] + v0;
        float v1 = s_tile[(lane + 31) * 33 + h];
        o[base + 32 + lane] = ab[base + 32 + lane] + v1;
        if (lane == 0) o[base + 64] = ab[base + 64] + s_tile[63 * 33 + h];
    }
}

// ---------------------------------------------------------------------------
// Inputs (metadata order):
//  0 attn_bias  f32 (64,32,65,65)
//  1 spatial_pos i32 (64,64,64)
//  2 edge_input  i32 (64,64,64,5,3)
//  3 attn_edge_type i32 (unused by reference)
//  4 W_edge     f32 (1025,32)
//  5 W_dist     f32 (131072,1)
//  6 W_spatial  f32 (512,32)
//  7 w_token    f32 (1,32)
// ---------------------------------------------------------------------------
extern "C" void kernel_launch(void* const* d_in, const int* in_sizes, int n_in,
                              void* d_out, int out_size)
{
    const float* attn_bias   = (const float*)d_in[0];
    const int*   spatial_pos = (const int*)  d_in[1];
    const int*   edge_input  = (const int*)  d_in[2];
    const float* W_edge      = (const float*)d_in[4];
    const float* W_dist      = (const float*)d_in[5];
    const float* W_spatial   = (const float*)d_in[6];
    const float* w_token     = (const float*)d_in[7];
    float*       out         = (float*)d_out;

    precompute_M<<<NEDGE, 160>>>(W_edge, W_dist);
    graph_attn_bias_kernel<<<64 * ROWLEN, 256>>>(
        attn_bias, spatial_pos, edge_input, W_spatial, w_token, out);
}

// round 3
// speedup vs baseline: 3.6308x; 1.4385x over previous
#include <cuda_runtime.h>
#include <cuda_fp16.h>

#define H      32
#define NN     64
#define MHD_   5
#define NEDGE  1025   // NUM_EDGE_EMB
#define ROWLEN 65     // N + 1

// Precombined table M[d][i][k] = sum_h W_edge[i][h] * Wd[d][h][k], fp16.
// Row = 32 halves = 64 B. 5*1025*32 halves = 328 KB static scratch.
__device__ __align__(16) __half d_M[MHD_ * NEDGE * H];

// ---------------------------------------------------------------------------
// Prologue: fold W_edge (1025x32) with Wd (5x32x32) into fp16 M.
// ---------------------------------------------------------------------------
__global__ __launch_bounds__(160) void precompute_M(
    const float* __restrict__ W_edge,
    const float* __restrict__ W_dist)
{
    int i    = blockIdx.x;            // edge-embedding row 0..1024
    int d    = threadIdx.x >> 5;      // 0..4
    int lane = threadIdx.x & 31;      // output head k

    float we = W_edge[i * H + lane];
    float acc = 0.f;
    #pragma unroll
    for (int h = 0; h < H; ++h) {
        float w = __shfl_sync(0xffffffffu, we, h);
        acc = fmaf(w, __ldg(&W_dist[(d * H + h) * H + lane]), acc);
    }
    d_M[(d * NEDGE + i) * H + lane] = __float2half(acc);
}

// ---------------------------------------------------------------------------
// Main kernel: grid = B*(N+1), 256 threads.
// Gather layout: 4 lanes per m, each lane loads uint4 = 8 heads (16 B).
// lane = (m_sub<<2) | q :  m = warp*8 + (lane>>2), heads [8q, 8q+8).
// Accumulation is half2 (HADD2/HFMA2), converted to fp32 once at the end.
// ---------------------------------------------------------------------------
__global__ __launch_bounds__(256, 6) void graph_attn_bias_kernel(
    const float* __restrict__ attn_bias,
    const int*   __restrict__ spatial_pos,
    const int*   __restrict__ edge_input,
    const float* __restrict__ W_spatial,
    const float* __restrict__ w_token,
    float*       __restrict__ out)
{
    const int bidx = blockIdx.x;
    const int b    = bidx / ROWLEN;
    const int r    = bidx - b * ROWLEN;
    const int tid  = threadIdx.x;
    const int warp = tid >> 5;
    const int lane = tid & 31;

    if (r == 0) {
        // Top border row: out[b,h,0,j] = attn_bias + w_token[h].
        const float* ab = attn_bias + (size_t)b * H * (ROWLEN * ROWLEN);
        float*       o  = out       + (size_t)b * H * (ROWLEN * ROWLEN);
        #pragma unroll
        for (int k = 0; k < 4; ++k) {
            int h = warp * 4 + k;
            float gt = __ldg(&w_token[h]);
            size_t base = (size_t)h * (ROWLEN * ROWLEN);
            o[base + lane]      = ab[base + lane]      + gt;
            o[base + 32 + lane] = ab[base + 32 + lane] + gt;
            if (lane == 0) o[base + 64] = ab[base + 64] + gt;
        }
        return;
    }
    const int n = r - 1;   // graph row 0..63

    __shared__ __align__(16) int s_eidx[NN * 15];  // 3.75 KB
    __shared__ int   s_sp[NN];
    __shared__ float s_tile[NN * 33];              // bias[m][h], pad 33

    // Stage edge indices (960 ints, 16B-aligned) as int4 + spatial row.
    {
        const int4* e4 = (const int4*)(edge_input + (size_t)(b * NN + n) * NN * 15);
        int4* s4 = (int4*)s_eidx;
        if (tid < NN * 15 / 4) s4[tid] = e4[tid];
        if (tid < NN) s_sp[tid] = spatial_pos[(size_t)(b * NN + n) * NN + tid];
    }
    __syncthreads();

    const int q = lane & 3;            // head-quad: heads 8q..8q+7
    const int m = warp * 8 + (lane >> 2);
    const int sp = s_sp[m];

    const uint4* M4 = (const uint4*)d_M;   // 4 uint4 per table row
    const uint4 zero4 = make_uint4(0u, 0u, 0u, 0u);

    __half2 acc0, acc1, acc2, acc3;
    {
        const uint zz = 0u;
        acc0 = acc1 = acc2 = acc3 = *(const __half2*)&zz;
    }

    #pragma unroll
    for (int d = 0; d < MHD_; ++d) {
        const int i0 = s_eidx[m * 15 + d * 3 + 0];
        const int i1 = s_eidx[m * 15 + d * 3 + 1];
        const int i2 = s_eidx[m * 15 + d * 3 + 2];
        uint4 v0 = zero4, v1 = zero4, v2 = zero4;
        if (i0) v0 = __ldg(&M4[(d * NEDGE + i0) * 4 + q]);
        if (i1) v1 = __ldg(&M4[(d * NEDGE + i1) * 4 + q]);
        if (i2) v2 = __ldg(&M4[(d * NEDGE + i2) * 4 + q]);

        const int c = (i0 != 0) + (i1 != 0) + (i2 != 0);
        // half2 reciprocal-of-count: 1, 1/2, 1/3 (0 if c==0)
        const unsigned rcbits = (c == 3) ? 0x35553555u
                              : (c == 2) ? 0x38003800u
                              : (c == 1) ? 0x3C003C00u : 0u;
        const __half2 rc2 = *(const __half2*)&rcbits;

        const __half2* h0 = (const __half2*)&v0;
        const __half2* h1 = (const __half2*)&v1;
        const __half2* h2 = (const __half2*)&v2;
        acc0 = __hfma2(__hadd2(__hadd2(h0[0], h1[0]), h2[0]), rc2, acc0);
        acc1 = __hfma2(__hadd2(__hadd2(h0[1], h1[1]), h2[1]), rc2, acc1);
        acc2 = __hfma2(__hadd2(__hadd2(h0[2], h1[2]), h2[2]), rc2, acc2);
        acc3 = __hfma2(__hadd2(__hadd2(h0[3], h1[3]), h2[3]), rc2, acc3);
    }

    int spc = sp - 1;
    spc = spc < 1 ? 1 : (spc > MHD_ ? MHD_ : spc);
    const float rs = (spc == 1) ? 1.f
                   : (spc == 2) ? 0.5f
                   : (spc == 3) ? (1.f / 3.f)
                   : (spc == 4) ? 0.25f : 0.2f;

    const float4 spbA = __ldg((const float4*)(W_spatial + sp * H + 8 * q));
    const float4 spbB = __ldg((const float4*)(W_spatial + sp * H + 8 * q + 4));
    const float2 f0 = __half22float2(acc0);
    const float2 f1 = __half22float2(acc1);
    const float2 f2 = __half22float2(acc2);
    const float2 f3 = __half22float2(acc3);

    float* t = s_tile + m * 33 + 8 * q;
    t[0] = fmaf(f0.x, rs, spbA.x);
    t[1] = fmaf(f0.y, rs, spbA.y);
    t[2] = fmaf(f1.x, rs, spbA.z);
    t[3] = fmaf(f1.y, rs, spbA.w);
    t[4] = fmaf(f2.x, rs, spbB.x);
    t[5] = fmaf(f2.y, rs, spbB.y);
    t[6] = fmaf(f3.x, rs, spbB.z);
    t[7] = fmaf(f3.y, rs, spbB.w);
    __syncthreads();

    // Write row (n+1): warp -> 4 heads, lane -> column; j==0 takes w_token.
    const float* ab = attn_bias + ((size_t)b * H * ROWLEN + (n + 1)) * ROWLEN;
    float*       o  = out       + ((size_t)b * H * ROWLEN + (n + 1)) * ROWLEN;
    #pragma unroll
    for (int k = 0; k < 4; ++k) {
        int h = warp * 4 + k;
        size_t base = (size_t)h * (ROWLEN * ROWLEN);
        float v0 = (lane == 0) ? __ldg(&w_token[h]) : s_tile[(lane - 1) * 33 + h];
        o[base + lane] = ab[base + lane] + v0;
        float v1 = s_tile[(lane + 31) * 33 + h];
        o[base + 32 + lane] = ab[base + 32 + lane] + v1;
        if (lane == 0) o[base + 64] = ab[base + 64] + s_tile[63 * 33 + h];
    }
}

// ---------------------------------------------------------------------------
// Inputs (metadata order):
//  0 attn_bias  f32 (64,32,65,65)   1 spatial_pos i32 (64,64,64)
//  2 edge_input i32 (64,64,64,5,3)  3 attn_edge_type (unused)
//  4 W_edge f32 (1025,32)  5 W_dist f32 (131072,1)
//  6 W_spatial f32 (512,32)  7 w_token f32 (1,32)
// ---------------------------------------------------------------------------
extern "C" void kernel_launch(void* const* d_in, const int* in_sizes, int n_in,
                              void* d_out, int out_size)
{
    const float* attn_bias   = (const float*)d_in[0];
    const int*   spatial_pos = (const int*)  d_in[1];
    const int*   edge_input  = (const int*)  d_in[2];
    const float* W_edge      = (const float*)d_in[4];
    const float* W_dist      = (const float*)d_in[5];
    const float* W_spatial   = (const float*)d_in[6];
    const float* w_token     = (const float*)d_in[7];
    float*       out         = (float*)d_out;

    precompute_M<<<NEDGE, 160>>>(W_edge, W_dist);
    graph_attn_bias_kernel<<<64 * ROWLEN, 256>>>(
        attn_bias, spatial_pos, edge_input, W_spatial, w_token, out);
}